// round 1
// baseline (speedup 1.0000x reference)
#include <cuda_runtime.h>
#include <math.h>

#define BB 64
#define HH 1024
#define EMBD 300
#define VV 50004
#define LL 1024
#define G3H 3072

// ---------------- scratch (static device memory; no allocations) ----------------
__device__ float g_x[BB * EMBD];
__device__ float g_part_gi[8 * BB * G3H];
__device__ float g_part_gh[8 * BB * G3H];
__device__ float g_hnew[BB * HH];
__device__ float g_cat[BB * 2 * HH];       // [context | h_new]
__device__ float g_part_wy[16 * BB * HH];
__device__ float g_wy[BB * HH];
__device__ float g_xwy[BB * LL];
__device__ float g_pm[BB * 16];
__device__ float g_ps[BB * 16];
__device__ float g_pctx[BB * 16 * HH];
__device__ float g_part_fu[16 * BB * HH];
__device__ float g_fused[BB * HH];
__device__ float g_lse[BB];

// ---------------- generic tiled GEMM body ----------------
// C[64 x N] = A[64 x K] @ W[N x K]^T   (partial over k in [ks0, ks1))
// tile: 64 x 128, 256 threads, micro 4(b) x 8(n), BK = 32
__device__ __forceinline__ void gemm_body(
    const float* __restrict__ A, const float* __restrict__ W,
    const float* __restrict__ bias, float* __restrict__ C,
    int N, int K, int ks0, int ks1, int act, bool direct)
{
    __shared__ float As[32][68];
    __shared__ float Ws[32][132];

    const int tid = threadIdx.x;
    const int nb  = blockIdx.x * 128;
    const int bq  = tid & 15;
    const int nq  = tid >> 4;
    const int b0  = bq * 4;
    const int n0  = nq * 8;

    float acc[4][8];
#pragma unroll
    for (int i = 0; i < 4; i++)
#pragma unroll
        for (int j = 0; j < 8; j++) acc[i][j] = 0.f;

    const int arow = tid >> 2;      // 0..63
    const int ac   = tid & 3;       // 0..3
    const int wrow = tid >> 1;      // 0..127
    const int wh   = tid & 1;       // 0..1

    for (int kb = ks0; kb < ks1; kb += 32) {
        // --- load A tile (64 x 32), store transposed As[k][row]
#pragma unroll
        for (int c = 0; c < 2; c++) {
            int kl = ac * 4 + c * 16;
            int k0 = kb + kl;
            float4 v;
            if (k0 + 4 <= ks1) {
                v = *(const float4*)(A + (size_t)arow * K + k0);
            } else {
                v.x = (k0     < ks1) ? A[(size_t)arow * K + k0    ] : 0.f;
                v.y = (k0 + 1 < ks1) ? A[(size_t)arow * K + k0 + 1] : 0.f;
                v.z = (k0 + 2 < ks1) ? A[(size_t)arow * K + k0 + 2] : 0.f;
                v.w = (k0 + 3 < ks1) ? A[(size_t)arow * K + k0 + 3] : 0.f;
            }
            As[kl    ][arow] = v.x;
            As[kl + 1][arow] = v.y;
            As[kl + 2][arow] = v.z;
            As[kl + 3][arow] = v.w;
        }
        // --- load W tile (128 x 32), store transposed Ws[k][wrow]
        int wr = nb + wrow;
#pragma unroll
        for (int q = 0; q < 4; q++) {
            int kl = wh * 16 + q * 4;
            int k0 = kb + kl;
            float4 v = make_float4(0.f, 0.f, 0.f, 0.f);
            if (wr < N) {
                if (k0 + 4 <= ks1) {
                    v = *(const float4*)(W + (size_t)wr * K + k0);
                } else {
                    v.x = (k0     < ks1) ? W[(size_t)wr * K + k0    ] : 0.f;
                    v.y = (k0 + 1 < ks1) ? W[(size_t)wr * K + k0 + 1] : 0.f;
                    v.z = (k0 + 2 < ks1) ? W[(size_t)wr * K + k0 + 2] : 0.f;
                    v.w = (k0 + 3 < ks1) ? W[(size_t)wr * K + k0 + 3] : 0.f;
                }
            }
            Ws[kl    ][wrow] = v.x;
            Ws[kl + 1][wrow] = v.y;
            Ws[kl + 2][wrow] = v.z;
            Ws[kl + 3][wrow] = v.w;
        }
        __syncthreads();

#pragma unroll
        for (int k = 0; k < 32; k++) {
            float4 a  = *(const float4*)&As[k][b0];
            float4 w0 = *(const float4*)&Ws[k][n0];
            float4 w1 = *(const float4*)&Ws[k][n0 + 4];
            float av[4] = {a.x, a.y, a.z, a.w};
            float wv[8] = {w0.x, w0.y, w0.z, w0.w, w1.x, w1.y, w1.z, w1.w};
#pragma unroll
            for (int i = 0; i < 4; i++)
#pragma unroll
                for (int j = 0; j < 8; j++)
                    acc[i][j] = fmaf(av[i], wv[j], acc[i][j]);
        }
        __syncthreads();
    }

    // --- store
#pragma unroll
    for (int i = 0; i < 4; i++) {
#pragma unroll
        for (int j = 0; j < 8; j++) {
            int n = nb + n0 + j;
            if (n < N) {
                float v = acc[i][j];
                if (direct) {
                    if (bias) v += bias[n];
                    if (act == 1) v = tanhf(v);
                }
                C[(size_t)(b0 + i) * N + n] = v;
            }
        }
    }
}

// ---------------- kernels ----------------
__global__ void k_gather(const int* __restrict__ input, const float* __restrict__ emb)
{
    int idx = blockIdx.x * 256 + threadIdx.x;
    if (idx < BB * EMBD) {
        int b = idx / EMBD, e = idx % EMBD;
        g_x[idx] = emb[(size_t)input[b] * EMBD + e];
    }
}

// grid (24, 8, 2): z=0 -> gi (K=300), z=1 -> gh (K=1024). split-K x8.
__global__ void __launch_bounds__(256) k_gru_gemm(
    const float* __restrict__ hidden,
    const float* __restrict__ w_ih, const float* __restrict__ w_hh)
{
    int split = blockIdx.y;
    if (blockIdx.z == 0) {
        int ks0 = split * 64;
        int ks1 = min(ks0 + 64, EMBD);
        gemm_body(g_x, w_ih, nullptr, g_part_gi + (size_t)split * BB * G3H,
                  G3H, EMBD, ks0, ks1, 0, false);
    } else {
        int ks0 = split * 128;
        int ks1 = min(ks0 + 128, HH);
        gemm_body(hidden, w_hh, nullptr, g_part_gh + (size_t)split * BB * G3H,
                  G3H, HH, ks0, ks1, 0, false);
    }
}

// combine GRU partials + gate math. writes g_hnew, g_cat[:,H:], d_out hidden.
__global__ void k_gru(const float* __restrict__ hidden,
                      const float* __restrict__ b_ih, const float* __restrict__ b_hh,
                      float* __restrict__ out_hid)
{
    int idx = blockIdx.x * 256 + threadIdx.x;
    if (idx >= BB * HH) return;
    int b = idx / HH, j = idx % HH;
    float gir = b_ih[j], giz = b_ih[j + HH], gin = b_ih[j + 2 * HH];
    float ghr = b_hh[j], ghz = b_hh[j + HH], ghn = b_hh[j + 2 * HH];
#pragma unroll
    for (int s = 0; s < 8; s++) {
        const float* pi = g_part_gi + (size_t)s * BB * G3H + (size_t)b * G3H;
        const float* ph = g_part_gh + (size_t)s * BB * G3H + (size_t)b * G3H;
        gir += pi[j]; giz += pi[j + HH]; gin += pi[j + 2 * HH];
        ghr += ph[j]; ghz += ph[j + HH]; ghn += ph[j + 2 * HH];
    }
    float r = 1.f / (1.f + __expf(-(gir + ghr)));
    float z = 1.f / (1.f + __expf(-(giz + ghz)));
    float n = tanhf(gin + r * ghn);
    float hn = (1.f - z) * n + z * hidden[idx];
    g_hnew[idx] = hn;
    g_cat[(size_t)b * 2 * HH + HH + j] = hn;
    out_hid[idx] = hn;
}

// Wy partial GEMM: grid (8, 16)
__global__ void __launch_bounds__(256) k_gemm_wy(const float* __restrict__ w_attn)
{
    int split = blockIdx.y;
    int ks0 = split * 64;
    int ks1 = min(ks0 + 64, HH);
    gemm_body(g_hnew, w_attn, nullptr, g_part_wy + (size_t)split * BB * HH,
              HH, HH, ks0, ks1, 0, false);
}

__global__ void k_combine_wy(const float* __restrict__ b_attn)
{
    int idx = blockIdx.x * 256 + threadIdx.x;
    if (idx >= BB * HH) return;
    float v = b_attn[idx % HH];
#pragma unroll
    for (int s = 0; s < 16; s++) v += g_part_wy[(size_t)s * BB * HH + idx];
    g_wy[idx] = v;
}

// attention pass 1: grid (16 chunks, 64 b), 256 threads (8 warps x 8 l's each)
__global__ void __launch_bounds__(256) k_attn1(
    const float* __restrict__ src, const int* __restrict__ mask)
{
    int b = blockIdx.y;
    int chunk = blockIdx.x;
    int l0 = chunk * 64;
    int tid = threadIdx.x, lane = tid & 31, wid = tid >> 5;

    float4 wyv[8];
#pragma unroll
    for (int q = 0; q < 8; q++)
        wyv[q] = *(const float4*)(g_wy + (size_t)b * HH + 4 * lane + 128 * q);

    float m = -1e30f, s = 0.f;
    float4 acc[8];
#pragma unroll
    for (int q = 0; q < 8; q++) acc[q] = make_float4(0.f, 0.f, 0.f, 0.f);

    for (int i = 0; i < 8; i++) {
        int l = l0 + wid * 8 + i;
        const float* sp = src + ((size_t)l * BB + b) * HH;
        float4 v[8];
#pragma unroll
        for (int q = 0; q < 8; q++)
            v[q] = *(const float4*)(sp + 4 * lane + 128 * q);
        float d = 0.f;
#pragma unroll
        for (int q = 0; q < 8; q++) {
            d = fmaf(v[q].x, wyv[q].x, d);
            d = fmaf(v[q].y, wyv[q].y, d);
            d = fmaf(v[q].z, wyv[q].z, d);
            d = fmaf(v[q].w, wyv[q].w, d);
        }
#pragma unroll
        for (int o = 16; o > 0; o >>= 1) d += __shfl_xor_sync(0xffffffffu, d, o);
        if (mask[(size_t)b * LL + l] != 0) d = -1e30f;
        if (lane == 0) g_xwy[(size_t)b * LL + l] = d;

        float nm = fmaxf(m, d);
        float sc = __expf(m - nm);
        float p  = __expf(d - nm);
        s = s * sc + p;
#pragma unroll
        for (int q = 0; q < 8; q++) {
            acc[q].x = acc[q].x * sc + p * v[q].x;
            acc[q].y = acc[q].y * sc + p * v[q].y;
            acc[q].z = acc[q].z * sc + p * v[q].z;
            acc[q].w = acc[q].w * sc + p * v[q].w;
        }
        m = nm;
    }

    __shared__ float sm[8], ss[8];
    __shared__ float sctx[8][1024];
    if (lane == 0) { sm[wid] = m; ss[wid] = s; }
    __syncthreads();
    float M = sm[0];
#pragma unroll
    for (int w = 1; w < 8; w++) M = fmaxf(M, sm[w]);
    float S = 0.f;
#pragma unroll
    for (int w = 0; w < 8; w++) S += ss[w] * __expf(sm[w] - M);

    float f = __expf(m - M);
#pragma unroll
    for (int q = 0; q < 8; q++) {
        float4 t = acc[q];
        t.x *= f; t.y *= f; t.z *= f; t.w *= f;
        *(float4*)&sctx[wid][4 * lane + 128 * q] = t;
    }
    __syncthreads();

    int h0 = tid * 4;
    float4 tot = make_float4(0.f, 0.f, 0.f, 0.f);
#pragma unroll
    for (int w = 0; w < 8; w++) {
        float4 t = *(const float4*)&sctx[w][h0];
        tot.x += t.x; tot.y += t.y; tot.z += t.z; tot.w += t.w;
    }
    int pidx = b * 16 + chunk;
    *(float4*)(g_pctx + (size_t)pidx * HH + h0) = tot;
    if (tid == 0) { g_pm[pidx] = M; g_ps[pidx] = S; }
}

// attention finalize: grid 64 (one block per b)
__global__ void k_attn2(float* __restrict__ out_scores)
{
    int b = blockIdx.x, t = threadIdx.x;
    __shared__ float fac[16];
    __shared__ float sM, sInvZ;
    if (t == 0) {
        float M = g_pm[b * 16];
        for (int c = 1; c < 16; c++) M = fmaxf(M, g_pm[b * 16 + c]);
        float Z = 0.f;
        for (int c = 0; c < 16; c++) Z += g_ps[b * 16 + c] * __expf(g_pm[b * 16 + c] - M);
        float invZ = 1.f / Z;
        for (int c = 0; c < 16; c++) fac[c] = __expf(g_pm[b * 16 + c] - M) * invZ;
        sM = M; sInvZ = invZ;
    }
    __syncthreads();

    int h0 = t * 4;
    float4 tot = make_float4(0.f, 0.f, 0.f, 0.f);
#pragma unroll
    for (int c = 0; c < 16; c++) {
        float4 v = *(const float4*)(g_pctx + (size_t)(b * 16 + c) * HH + h0);
        float fc = fac[c];
        tot.x += v.x * fc; tot.y += v.y * fc; tot.z += v.z * fc; tot.w += v.w * fc;
    }
    *(float4*)(g_cat + (size_t)b * 2 * HH + h0) = tot;

    float M = sM, invZ = sInvZ;
#pragma unroll
    for (int r = 0; r < 4; r++) {
        int l = t + 256 * r;
        float sc = __expf(g_xwy[(size_t)b * LL + l] - M) * invZ;
        out_scores[(size_t)b * LL + l] = sc;
    }
}

// fused partial GEMM: grid (8, 16)
__global__ void __launch_bounds__(256) k_gemm_fu(const float* __restrict__ w_lin)
{
    int split = blockIdx.y;
    int ks0 = split * 128;
    int ks1 = min(ks0 + 128, 2 * HH);
    gemm_body(g_cat, w_lin, nullptr, g_part_fu + (size_t)split * BB * HH,
              HH, 2 * HH, ks0, ks1, 0, false);
}

__global__ void k_combine_fu(const float* __restrict__ b_lin)
{
    int idx = blockIdx.x * 256 + threadIdx.x;
    if (idx >= BB * HH) return;
    float v = b_lin[idx % HH];
#pragma unroll
    for (int s = 0; s < 16; s++) v += g_part_fu[(size_t)s * BB * HH + idx];
    g_fused[idx] = tanhf(v);
}

// logits GEMM (direct, bias): grid (391, 1)
__global__ void __launch_bounds__(256) k_gemm_logits(
    const float* __restrict__ w_out, const float* __restrict__ b_out,
    float* __restrict__ out_logp)
{
    gemm_body(g_fused, w_out, b_out, out_logp, VV, HH, 0, HH, 0, true);
}

// per-row logsumexp over V: grid 64
__global__ void k_lse(const float* __restrict__ logits)
{
    int b = blockIdx.x, t = threadIdx.x;
    float m = -1e30f, s = 0.f;
    for (int n = t; n < VV; n += 256) {
        float v = logits[(size_t)b * VV + n];
        float nm = fmaxf(m, v);
        s = s * __expf(m - nm) + __expf(v - nm);
        m = nm;
    }
    __shared__ float sm[256], ss[256];
    sm[t] = m; ss[t] = s;
    __syncthreads();
    for (int o = 128; o > 0; o >>= 1) {
        if (t < o) {
            float m2 = sm[t + o], s2 = ss[t + o];
            float nm = fmaxf(sm[t], m2);
            ss[t] = ss[t] * __expf(sm[t] - nm) + s2 * __expf(m2 - nm);
            sm[t] = nm;
        }
        __syncthreads();
    }
    if (t == 0) g_lse[b] = sm[0] + logf(ss[0]);
}

__global__ void k_sub(float* __restrict__ logp)
{
    int n = blockIdx.x * 256 + threadIdx.x;
    int b = blockIdx.y;
    if (n < VV) logp[(size_t)b * VV + n] -= g_lse[b];
}

// ---------------- launcher ----------------
extern "C" void kernel_launch(void* const* d_in, const int* in_sizes, int n_in,
                              void* d_out, int out_size)
{
    const int*   input  = (const int*)  d_in[0];
    const float* hidden = (const float*)d_in[1];
    const float* src    = (const float*)d_in[2];
    const int*   mask   = (const int*)  d_in[3];
    const float* emb    = (const float*)d_in[4];
    const float* w_ih   = (const float*)d_in[5];
    const float* w_hh   = (const float*)d_in[6];
    const float* b_ih   = (const float*)d_in[7];
    const float* b_hh   = (const float*)d_in[8];
    const float* w_attn = (const float*)d_in[9];
    const float* b_attn = (const float*)d_in[10];
    const float* w_lin  = (const float*)d_in[11];
    const float* b_lin  = (const float*)d_in[12];
    const float* w_out  = (const float*)d_in[13];
    const float* b_out  = (const float*)d_in[14];

    float* out        = (float*)d_out;
    float* out_logp   = out;                                   // [64 x 50004]
    float* out_hid    = out + (size_t)BB * VV;                 // [1 x 64 x 1024]
    float* out_scores = out_hid + (size_t)BB * HH;             // [64 x 1024]

    k_gather<<<(BB * EMBD + 255) / 256, 256>>>(input, emb);
    k_gru_gemm<<<dim3(24, 8, 2), 256>>>(hidden, w_ih, w_hh);
    k_gru<<<(BB * HH + 255) / 256, 256>>>(hidden, b_ih, b_hh, out_hid);
    k_gemm_wy<<<dim3(8, 16), 256>>>(w_attn);
    k_combine_wy<<<(BB * HH + 255) / 256, 256>>>(b_attn);
    k_attn1<<<dim3(16, BB), 256>>>(src, mask);
    k_attn2<<<BB, 256>>>(out_scores);
    k_gemm_fu<<<dim3(8, 16), 256>>>(w_lin);
    k_combine_fu<<<(BB * HH + 255) / 256, 256>>>(b_lin);
    k_gemm_logits<<<dim3((VV + 127) / 128, 1), 256>>>(w_out, b_out, out_logp);
    k_lse<<<BB, 256>>>(out_logp);
    k_sub<<<dim3((VV + 255) / 256, BB), 256>>>(out_logp);
}

// round 2
// speedup vs baseline: 1.5952x; 1.5952x over previous
#include <cuda_runtime.h>
#include <cuda_bf16.h>
#include <math.h>

#define BB 64
#define HH 1024
#define EMBD 300
#define VV 50004
#define LL 1024
#define G3H 3072

// ---------------- scratch (static device memory; no allocations) ----------------
__device__ float g_x[BB * EMBD];
__device__ float g_part_gi[8 * BB * G3H];
__device__ float g_part_gh[8 * BB * G3H];
__device__ float g_hnew[BB * HH];
__device__ float g_cat[BB * 2 * HH];       // [context | h_new]
__device__ float g_part_wy[16 * BB * HH];
__device__ float g_wy[BB * HH];
__device__ float g_xwy[BB * LL];
__device__ float g_pm[BB * 16];
__device__ float g_ps[BB * 16];
__device__ float g_pctx[BB * 16 * HH];
__device__ float g_part_fu[16 * BB * HH];
__device__ __nv_bfloat16 g_fused_b16[BB * HH];
__device__ float g_lse[BB];

// ---------------- generic tiled GEMM body (fp32, for the small GEMMs) ----------------
// C[64 x N] = A[64 x K] @ W[N x K]^T   (partial over k in [ks0, ks1))
__device__ __forceinline__ void gemm_body(
    const float* __restrict__ A, const float* __restrict__ W,
    const float* __restrict__ bias, float* __restrict__ C,
    int N, int K, int ks0, int ks1, int act, bool direct)
{
    __shared__ float As[32][68];
    __shared__ float Ws[32][132];

    const int tid = threadIdx.x;
    const int nb  = blockIdx.x * 128;
    const int bq  = tid & 15;
    const int nq  = tid >> 4;
    const int b0  = bq * 4;
    const int n0  = nq * 8;

    float acc[4][8];
#pragma unroll
    for (int i = 0; i < 4; i++)
#pragma unroll
        for (int j = 0; j < 8; j++) acc[i][j] = 0.f;

    const int arow = tid >> 2;
    const int ac   = tid & 3;
    const int wrow = tid >> 1;
    const int wh   = tid & 1;

    for (int kb = ks0; kb < ks1; kb += 32) {
#pragma unroll
        for (int c = 0; c < 2; c++) {
            int kl = ac * 4 + c * 16;
            int k0 = kb + kl;
            float4 v;
            if (k0 + 4 <= ks1) {
                v = *(const float4*)(A + (size_t)arow * K + k0);
            } else {
                v.x = (k0     < ks1) ? A[(size_t)arow * K + k0    ] : 0.f;
                v.y = (k0 + 1 < ks1) ? A[(size_t)arow * K + k0 + 1] : 0.f;
                v.z = (k0 + 2 < ks1) ? A[(size_t)arow * K + k0 + 2] : 0.f;
                v.w = (k0 + 3 < ks1) ? A[(size_t)arow * K + k0 + 3] : 0.f;
            }
            As[kl    ][arow] = v.x;
            As[kl + 1][arow] = v.y;
            As[kl + 2][arow] = v.z;
            As[kl + 3][arow] = v.w;
        }
        int wr = nb + wrow;
#pragma unroll
        for (int q = 0; q < 4; q++) {
            int kl = wh * 16 + q * 4;
            int k0 = kb + kl;
            float4 v = make_float4(0.f, 0.f, 0.f, 0.f);
            if (wr < N) {
                if (k0 + 4 <= ks1) {
                    v = *(const float4*)(W + (size_t)wr * K + k0);
                } else {
                    v.x = (k0     < ks1) ? W[(size_t)wr * K + k0    ] : 0.f;
                    v.y = (k0 + 1 < ks1) ? W[(size_t)wr * K + k0 + 1] : 0.f;
                    v.z = (k0 + 2 < ks1) ? W[(size_t)wr * K + k0 + 2] : 0.f;
                    v.w = (k0 + 3 < ks1) ? W[(size_t)wr * K + k0 + 3] : 0.f;
                }
            }
            Ws[kl    ][wrow] = v.x;
            Ws[kl + 1][wrow] = v.y;
            Ws[kl + 2][wrow] = v.z;
            Ws[kl + 3][wrow] = v.w;
        }
        __syncthreads();

#pragma unroll
        for (int k = 0; k < 32; k++) {
            float4 a  = *(const float4*)&As[k][b0];
            float4 w0 = *(const float4*)&Ws[k][n0];
            float4 w1 = *(const float4*)&Ws[k][n0 + 4];
            float av[4] = {a.x, a.y, a.z, a.w};
            float wv[8] = {w0.x, w0.y, w0.z, w0.w, w1.x, w1.y, w1.z, w1.w};
#pragma unroll
            for (int i = 0; i < 4; i++)
#pragma unroll
                for (int j = 0; j < 8; j++)
                    acc[i][j] = fmaf(av[i], wv[j], acc[i][j]);
        }
        __syncthreads();
    }

#pragma unroll
    for (int i = 0; i < 4; i++) {
#pragma unroll
        for (int j = 0; j < 8; j++) {
            int n = nb + n0 + j;
            if (n < N) {
                float v = acc[i][j];
                if (direct) {
                    if (bias) v += bias[n];
                    if (act == 1) v = tanhf(v);
                }
                C[(size_t)(b0 + i) * N + n] = v;
            }
        }
    }
}

// ---------------- kernels ----------------
__global__ void k_gather(const int* __restrict__ input, const float* __restrict__ emb)
{
    int idx = blockIdx.x * 256 + threadIdx.x;
    if (idx < BB * EMBD) {
        int b = idx / EMBD, e = idx % EMBD;
        g_x[idx] = emb[(size_t)input[b] * EMBD + e];
    }
}

__global__ void __launch_bounds__(256) k_gru_gemm(
    const float* __restrict__ hidden,
    const float* __restrict__ w_ih, const float* __restrict__ w_hh)
{
    int split = blockIdx.y;
    if (blockIdx.z == 0) {
        int ks0 = split * 64;
        int ks1 = min(ks0 + 64, EMBD);
        gemm_body(g_x, w_ih, nullptr, g_part_gi + (size_t)split * BB * G3H,
                  G3H, EMBD, ks0, ks1, 0, false);
    } else {
        int ks0 = split * 128;
        int ks1 = min(ks0 + 128, HH);
        gemm_body(hidden, w_hh, nullptr, g_part_gh + (size_t)split * BB * G3H,
                  G3H, HH, ks0, ks1, 0, false);
    }
}

__global__ void k_gru(const float* __restrict__ hidden,
                      const float* __restrict__ b_ih, const float* __restrict__ b_hh,
                      float* __restrict__ out_hid)
{
    int idx = blockIdx.x * 256 + threadIdx.x;
    if (idx >= BB * HH) return;
    int b = idx / HH, j = idx % HH;
    float gir = b_ih[j], giz = b_ih[j + HH], gin = b_ih[j + 2 * HH];
    float ghr = b_hh[j], ghz = b_hh[j + HH], ghn = b_hh[j + 2 * HH];
#pragma unroll
    for (int s = 0; s < 8; s++) {
        const float* pi = g_part_gi + (size_t)s * BB * G3H + (size_t)b * G3H;
        const float* ph = g_part_gh + (size_t)s * BB * G3H + (size_t)b * G3H;
        gir += pi[j]; giz += pi[j + HH]; gin += pi[j + 2 * HH];
        ghr += ph[j]; ghz += ph[j + HH]; ghn += ph[j + 2 * HH];
    }
    float r = 1.f / (1.f + __expf(-(gir + ghr)));
    float z = 1.f / (1.f + __expf(-(giz + ghz)));
    float n = tanhf(gin + r * ghn);
    float hn = (1.f - z) * n + z * hidden[idx];
    g_hnew[idx] = hn;
    g_cat[(size_t)b * 2 * HH + HH + j] = hn;
    out_hid[idx] = hn;
}

__global__ void __launch_bounds__(256) k_gemm_wy(const float* __restrict__ w_attn)
{
    int split = blockIdx.y;
    int ks0 = split * 64;
    int ks1 = min(ks0 + 64, HH);
    gemm_body(g_hnew, w_attn, nullptr, g_part_wy + (size_t)split * BB * HH,
              HH, HH, ks0, ks1, 0, false);
}

__global__ void k_combine_wy(const float* __restrict__ b_attn)
{
    int idx = blockIdx.x * 256 + threadIdx.x;
    if (idx >= BB * HH) return;
    float v = b_attn[idx % HH];
#pragma unroll
    for (int s = 0; s < 16; s++) v += g_part_wy[(size_t)s * BB * HH + idx];
    g_wy[idx] = v;
}

__global__ void __launch_bounds__(256) k_attn1(
    const float* __restrict__ src, const int* __restrict__ mask)
{
    int b = blockIdx.y;
    int chunk = blockIdx.x;
    int l0 = chunk * 64;
    int tid = threadIdx.x, lane = tid & 31, wid = tid >> 5;

    float4 wyv[8];
#pragma unroll
    for (int q = 0; q < 8; q++)
        wyv[q] = *(const float4*)(g_wy + (size_t)b * HH + 4 * lane + 128 * q);

    float m = -1e30f, s = 0.f;
    float4 acc[8];
#pragma unroll
    for (int q = 0; q < 8; q++) acc[q] = make_float4(0.f, 0.f, 0.f, 0.f);

    for (int i = 0; i < 8; i++) {
        int l = l0 + wid * 8 + i;
        const float* sp = src + ((size_t)l * BB + b) * HH;
        float4 v[8];
#pragma unroll
        for (int q = 0; q < 8; q++)
            v[q] = *(const float4*)(sp + 4 * lane + 128 * q);
        float d = 0.f;
#pragma unroll
        for (int q = 0; q < 8; q++) {
            d = fmaf(v[q].x, wyv[q].x, d);
            d = fmaf(v[q].y, wyv[q].y, d);
            d = fmaf(v[q].z, wyv[q].z, d);
            d = fmaf(v[q].w, wyv[q].w, d);
        }
#pragma unroll
        for (int o = 16; o > 0; o >>= 1) d += __shfl_xor_sync(0xffffffffu, d, o);
        if (mask[(size_t)b * LL + l] != 0) d = -1e30f;
        if (lane == 0) g_xwy[(size_t)b * LL + l] = d;

        float nm = fmaxf(m, d);
        float sc = __expf(m - nm);
        float p  = __expf(d - nm);
        s = s * sc + p;
#pragma unroll
        for (int q = 0; q < 8; q++) {
            acc[q].x = acc[q].x * sc + p * v[q].x;
            acc[q].y = acc[q].y * sc + p * v[q].y;
            acc[q].z = acc[q].z * sc + p * v[q].z;
            acc[q].w = acc[q].w * sc + p * v[q].w;
        }
        m = nm;
    }

    __shared__ float sm[8], ss[8];
    __shared__ float sctx[8][1024];
    if (lane == 0) { sm[wid] = m; ss[wid] = s; }
    __syncthreads();
    float M = sm[0];
#pragma unroll
    for (int w = 1; w < 8; w++) M = fmaxf(M, sm[w]);
    float S = 0.f;
#pragma unroll
    for (int w = 0; w < 8; w++) S += ss[w] * __expf(sm[w] - M);

    float f = __expf(m - M);
#pragma unroll
    for (int q = 0; q < 8; q++) {
        float4 t = acc[q];
        t.x *= f; t.y *= f; t.z *= f; t.w *= f;
        *(float4*)&sctx[wid][4 * lane + 128 * q] = t;
    }
    __syncthreads();

    int h0 = tid * 4;
    float4 tot = make_float4(0.f, 0.f, 0.f, 0.f);
#pragma unroll
    for (int w = 0; w < 8; w++) {
        float4 t = *(const float4*)&sctx[w][h0];
        tot.x += t.x; tot.y += t.y; tot.z += t.z; tot.w += t.w;
    }
    int pidx = b * 16 + chunk;
    *(float4*)(g_pctx + (size_t)pidx * HH + h0) = tot;
    if (tid == 0) { g_pm[pidx] = M; g_ps[pidx] = S; }
}

__global__ void k_attn2(float* __restrict__ out_scores)
{
    int b = blockIdx.x, t = threadIdx.x;
    __shared__ float fac[16];
    __shared__ float sM, sInvZ;
    if (t == 0) {
        float M = g_pm[b * 16];
        for (int c = 1; c < 16; c++) M = fmaxf(M, g_pm[b * 16 + c]);
        float Z = 0.f;
        for (int c = 0; c < 16; c++) Z += g_ps[b * 16 + c] * __expf(g_pm[b * 16 + c] - M);
        float invZ = 1.f / Z;
        for (int c = 0; c < 16; c++) fac[c] = __expf(g_pm[b * 16 + c] - M) * invZ;
        sM = M; sInvZ = invZ;
    }
    __syncthreads();

    int h0 = t * 4;
    float4 tot = make_float4(0.f, 0.f, 0.f, 0.f);
#pragma unroll
    for (int c = 0; c < 16; c++) {
        float4 v = *(const float4*)(g_pctx + (size_t)(b * 16 + c) * HH + h0);
        float fc = fac[c];
        tot.x += v.x * fc; tot.y += v.y * fc; tot.z += v.z * fc; tot.w += v.w * fc;
    }
    *(float4*)(g_cat + (size_t)b * 2 * HH + h0) = tot;

    float M = sM, invZ = sInvZ;
#pragma unroll
    for (int r = 0; r < 4; r++) {
        int l = t + 256 * r;
        float sc = __expf(g_xwy[(size_t)b * LL + l] - M) * invZ;
        out_scores[(size_t)b * LL + l] = sc;
    }
}

__global__ void __launch_bounds__(256) k_gemm_fu(const float* __restrict__ w_lin)
{
    int split = blockIdx.y;
    int ks0 = split * 128;
    int ks1 = min(ks0 + 128, 2 * HH);
    gemm_body(g_cat, w_lin, nullptr, g_part_fu + (size_t)split * BB * HH,
              HH, 2 * HH, ks0, ks1, 0, false);
}

__global__ void k_combine_fu(const float* __restrict__ b_lin)
{
    int idx = blockIdx.x * 256 + threadIdx.x;
    if (idx >= BB * HH) return;
    float v = b_lin[idx % HH];
#pragma unroll
    for (int s = 0; s < 16; s++) v += g_part_fu[(size_t)s * BB * HH + idx];
    g_fused_b16[idx] = __float2bfloat16(tanhf(v));
}

// ---------------- logits GEMM on tensor cores ----------------
// C[64 x 50004] = A_bf16[64 x 1024] @ W[50004 x 1024]^T (+ bias)
// W converted fp32 -> bf16 on the fly. Tile: BM=64, BN=128, BK=64.
// 8 warps: 2(m) x 4(n); each warp 2x4 m16n8k16 frags.
#define LBN 128
#define LBK 64
#define WPAD 72   // bf16 row stride in smem (144 B -> 8 row-groups cover all 32 banks)

__global__ void __launch_bounds__(256) k_logits_mma(
    const float* __restrict__ w_out, const float* __restrict__ b_out,
    float* __restrict__ out_logp)
{
    __shared__ __nv_bfloat16 As[64][WPAD];
    __shared__ __nv_bfloat16 Ws[LBN][WPAD];

    const int tid  = threadIdx.x;
    const int lane = tid & 31;
    const int wid  = tid >> 5;
    const int nb   = blockIdx.x * LBN;
    const int warp_m = wid >> 2;      // 0..1
    const int warp_n = wid & 3;       // 0..3
    const int g = lane >> 2;          // 0..7
    const int q = lane & 3;           // 0..3

    float acc[2][4][4];
#pragma unroll
    for (int tm = 0; tm < 2; tm++)
#pragma unroll
        for (int tn = 0; tn < 4; tn++)
#pragma unroll
            for (int c = 0; c < 4; c++) acc[tm][tn][c] = 0.f;

    const int ar = tid >> 2;          // 0..63 (A row)
    const int as = tid & 3;           // 0..3  (A 16-elem segment)
    const int wr = tid >> 2;          // 0..63 (W row base)
    const int wc = tid & 3;           // 0..3  (W float4 phase)

    for (int kb = 0; kb < HH; kb += LBK) {
        // load A tile (64 x 64 bf16) from precomputed bf16 activations
        {
            const uint4* src4 = (const uint4*)(g_fused_b16 + (size_t)ar * HH + kb + as * 16);
            uint4 v0 = src4[0];
            uint4 v1 = src4[1];
            *(uint4*)(&As[ar][as * 16])     = v0;
            *(uint4*)(&As[ar][as * 16 + 8]) = v1;
        }
        // load W tile (128 x 64 fp32) -> convert -> smem bf16
#pragma unroll
        for (int half = 0; half < 2; half++) {
            int n = nb + wr + half * 64;
            const float* wp = w_out + (size_t)n * HH + kb;
            bool ok = (n < VV);
#pragma unroll
            for (int j = 0; j < 4; j++) {
                int f4 = wc + j * 4;  // float4 index within the 64-col row
                float4 v = ok ? *(const float4*)(wp + f4 * 4)
                              : make_float4(0.f, 0.f, 0.f, 0.f);
                __nv_bfloat162 p0 = __floats2bfloat162_rn(v.x, v.y);
                __nv_bfloat162 p1 = __floats2bfloat162_rn(v.z, v.w);
                uint2 pk;
                pk.x = *(unsigned int*)&p0;
                pk.y = *(unsigned int*)&p1;
                *(uint2*)(&Ws[wr + half * 64][f4 * 4]) = pk;
            }
        }
        __syncthreads();

#pragma unroll
        for (int kk = 0; kk < LBK; kk += 16) {
            unsigned int a[2][4];
#pragma unroll
            for (int tm = 0; tm < 2; tm++) {
                int m = warp_m * 32 + tm * 16;
                a[tm][0] = *(const unsigned int*)&As[m + g    ][kk + q * 2];
                a[tm][1] = *(const unsigned int*)&As[m + g + 8][kk + q * 2];
                a[tm][2] = *(const unsigned int*)&As[m + g    ][kk + 8 + q * 2];
                a[tm][3] = *(const unsigned int*)&As[m + g + 8][kk + 8 + q * 2];
            }
#pragma unroll
            for (int tn = 0; tn < 4; tn++) {
                int n = warp_n * 32 + tn * 8;
                unsigned int b0 = *(const unsigned int*)&Ws[n + g][kk + q * 2];
                unsigned int b1 = *(const unsigned int*)&Ws[n + g][kk + 8 + q * 2];
#pragma unroll
                for (int tm = 0; tm < 2; tm++) {
                    asm volatile(
                        "mma.sync.aligned.m16n8k16.row.col.f32.bf16.bf16.f32 "
                        "{%0,%1,%2,%3}, {%4,%5,%6,%7}, {%8,%9}, {%0,%1,%2,%3};\n"
                        : "+f"(acc[tm][tn][0]), "+f"(acc[tm][tn][1]),
                          "+f"(acc[tm][tn][2]), "+f"(acc[tm][tn][3])
                        : "r"(a[tm][0]), "r"(a[tm][1]), "r"(a[tm][2]), "r"(a[tm][3]),
                          "r"(b0), "r"(b1));
                }
            }
        }
        __syncthreads();
    }

    // epilogue: add bias, store fp32
#pragma unroll
    for (int tm = 0; tm < 2; tm++) {
#pragma unroll
        for (int tn = 0; tn < 4; tn++) {
            int m0 = warp_m * 32 + tm * 16 + g;
            int n  = nb + warp_n * 32 + tn * 8 + q * 2;
            if (n + 1 < VV) {
                float bz0 = b_out[n], bz1 = b_out[n + 1];
                float2 r0 = make_float2(acc[tm][tn][0] + bz0, acc[tm][tn][1] + bz1);
                float2 r1 = make_float2(acc[tm][tn][2] + bz0, acc[tm][tn][3] + bz1);
                *(float2*)(out_logp + (size_t)m0 * VV + n)       = r0;
                *(float2*)(out_logp + (size_t)(m0 + 8) * VV + n) = r1;
            } else {
                for (int c = 0; c < 2; c++) {
                    if (n + c < VV) {
                        float bz = b_out[n + c];
                        out_logp[(size_t)m0 * VV + n + c]       = acc[tm][tn][c] + bz;
                        out_logp[(size_t)(m0 + 8) * VV + n + c] = acc[tm][tn][2 + c] + bz;
                    }
                }
            }
        }
    }
}

// per-row logsumexp over V: grid 64
__global__ void k_lse(const float* __restrict__ logits)
{
    int b = blockIdx.x, t = threadIdx.x;
    float m = -1e30f, s = 0.f;
    for (int n = t; n < VV; n += 256) {
        float v = logits[(size_t)b * VV + n];
        float nm = fmaxf(m, v);
        s = s * __expf(m - nm) + __expf(v - nm);
        m = nm;
    }
    __shared__ float sm[256], ss[256];
    sm[t] = m; ss[t] = s;
    __syncthreads();
    for (int o = 128; o > 0; o >>= 1) {
        if (t < o) {
            float m2 = sm[t + o], s2 = ss[t + o];
            float nm = fmaxf(sm[t], m2);
            ss[t] = ss[t] * __expf(sm[t] - nm) + s2 * __expf(m2 - nm);
            sm[t] = nm;
        }
        __syncthreads();
    }
    if (t == 0) g_lse[b] = sm[0] + logf(ss[0]);
}

__global__ void k_sub(float* __restrict__ logp)
{
    int n = blockIdx.x * 256 + threadIdx.x;
    int b = blockIdx.y;
    if (n < VV) logp[(size_t)b * VV + n] -= g_lse[b];
}

// ---------------- launcher ----------------
extern "C" void kernel_launch(void* const* d_in, const int* in_sizes, int n_in,
                              void* d_out, int out_size)
{
    const int*   input  = (const int*)  d_in[0];
    const float* hidden = (const float*)d_in[1];
    const float* src    = (const float*)d_in[2];
    const int*   mask   = (const int*)  d_in[3];
    const float* emb    = (const float*)d_in[4];
    const float* w_ih   = (const float*)d_in[5];
    const float* w_hh   = (const float*)d_in[6];
    const float* b_ih   = (const float*)d_in[7];
    const float* b_hh   = (const float*)d_in[8];
    const float* w_attn = (const float*)d_in[9];
    const float* b_attn = (const float*)d_in[10];
    const float* w_lin  = (const float*)d_in[11];
    const float* b_lin  = (const float*)d_in[12];
    const float* w_out  = (const float*)d_in[13];
    const float* b_out  = (const float*)d_in[14];

    float* out        = (float*)d_out;
    float* out_logp   = out;                                   // [64 x 50004]
    float* out_hid    = out + (size_t)BB * VV;                 // [1 x 64 x 1024]
    float* out_scores = out_hid + (size_t)BB * HH;             // [64 x 1024]

    k_gather<<<(BB * EMBD + 255) / 256, 256>>>(input, emb);
    k_gru_gemm<<<dim3(24, 8, 2), 256>>>(hidden, w_ih, w_hh);
    k_gru<<<(BB * HH + 255) / 256, 256>>>(hidden, b_ih, b_hh, out_hid);
    k_gemm_wy<<<dim3(8, 16), 256>>>(w_attn);
    k_combine_wy<<<(BB * HH + 255) / 256, 256>>>(b_attn);
    k_attn1<<<dim3(16, BB), 256>>>(src, mask);
    k_attn2<<<BB, 256>>>(out_scores);
    k_gemm_fu<<<dim3(8, 16), 256>>>(w_lin);
    k_combine_fu<<<(BB * HH + 255) / 256, 256>>>(b_lin);
    k_logits_mma<<<(VV + LBN - 1) / LBN, 256>>>(w_out, b_out, out_logp);
    k_lse<<<BB, 256>>>(out_logp);
    k_sub<<<dim3((VV + 255) / 256, BB), 256>>>(out_logp);
}

// round 3
// speedup vs baseline: 1.8931x; 1.1868x over previous
#include <cuda_runtime.h>
#include <cuda_bf16.h>
#include <math.h>

#define BB 64
#define HH 1024
#define EMBD 300
#define VV 50004
#define LL 1024
#define G3H 3072

// split counts
#define SPL_GI 5     // K=300, 64-chunks
#define SPL_GH 8     // K=1024, 128-slices
#define SPL_WY 16    // K=1024, 64-slices
#define SPL_FU 16    // K=2048, 128-slices

// ---------------- scratch (static device memory; no allocations) ----------------
__device__ float g_part_gi[SPL_GI * BB * G3H];
__device__ float g_part_gh[SPL_GH * BB * G3H];
__device__ float g_hnew[BB * HH];
__device__ float g_cat[BB * 2 * HH];       // [context | h_new]
__device__ float g_part_wy[SPL_WY * BB * HH];
__device__ float g_wy[BB * HH];
__device__ float g_xwy[BB * LL];
__device__ float g_pm[BB * 16];
__device__ float g_ps[BB * 16];
__device__ float g_pctx[BB * 16 * HH];
__device__ float g_part_fu[SPL_FU * BB * HH];
__device__ __nv_bfloat16 g_fused_b16[BB * HH];
__device__ float g_lse[BB];

__device__ __forceinline__ float to_tf32(float x)
{
    float r;
    asm("cvt.rna.tf32.f32 %0, %1;" : "=f"(r) : "f"(x));
    return r;
}

// ---------------- tf32 tensor-core GEMM (small GEMMs) ----------------
// Cpart[64 x N] = A[64 x k-slice] @ W[N x K]^T over k in [ks0, ks1)
// tile 64 x 128, 256 threads, 8 warps = 2(m) x 4(n), BK = 32
__device__ __forceinline__ void tf32_gemm(
    const float* __restrict__ A, int lda,
    const int* __restrict__ inp, const float* __restrict__ emb, bool gather,
    const float* __restrict__ W, int ldw, int N,
    float* __restrict__ Cpart, int ks0, int ks1)
{
    __shared__ float As[64][36];
    __shared__ float Ws[128][36];

    const int tid  = threadIdx.x;
    const int lane = tid & 31;
    const int wid  = tid >> 5;
    const int nb   = blockIdx.x * 128;
    const int warp_m = wid >> 2;
    const int warp_n = wid & 3;
    const int g = lane >> 2;
    const int q = lane & 3;

    float acc[2][4][4];
#pragma unroll
    for (int tm = 0; tm < 2; tm++)
#pragma unroll
        for (int tn = 0; tn < 4; tn++)
#pragma unroll
            for (int c = 0; c < 4; c++) acc[tm][tn][c] = 0.f;

    for (int kb = ks0; kb < ks1; kb += 32) {
#pragma unroll
        for (int t = 0; t < 2; t++) {
            int idx = tid + 256 * t;
            int row = idx >> 3;
            int c4  = idx & 7;
            int k0  = kb + c4 * 4;
            float4 v = make_float4(0.f, 0.f, 0.f, 0.f);
            if (k0 + 4 <= ks1) {
                const float* ap = gather ? (emb + (size_t)inp[row] * lda)
                                         : (A + (size_t)row * lda);
                v = *(const float4*)(ap + k0);
            }
            As[row][c4 * 4 + 0] = to_tf32(v.x);
            As[row][c4 * 4 + 1] = to_tf32(v.y);
            As[row][c4 * 4 + 2] = to_tf32(v.z);
            As[row][c4 * 4 + 3] = to_tf32(v.w);
        }
#pragma unroll
        for (int t = 0; t < 4; t++) {
            int idx = tid + 256 * t;
            int row = idx >> 3;
            int c4  = idx & 7;
            int k0  = kb + c4 * 4;
            int n   = nb + row;
            float4 v = make_float4(0.f, 0.f, 0.f, 0.f);
            if (n < N && k0 + 4 <= ks1)
                v = *(const float4*)(W + (size_t)n * ldw + k0);
            Ws[row][c4 * 4 + 0] = to_tf32(v.x);
            Ws[row][c4 * 4 + 1] = to_tf32(v.y);
            Ws[row][c4 * 4 + 2] = to_tf32(v.z);
            Ws[row][c4 * 4 + 3] = to_tf32(v.w);
        }
        __syncthreads();

#pragma unroll
        for (int kk = 0; kk < 32; kk += 8) {
            unsigned int a[2][4];
#pragma unroll
            for (int tm = 0; tm < 2; tm++) {
                int m = warp_m * 32 + tm * 16;
                a[tm][0] = __float_as_uint(As[m + g    ][kk + q    ]);
                a[tm][1] = __float_as_uint(As[m + g + 8][kk + q    ]);
                a[tm][2] = __float_as_uint(As[m + g    ][kk + q + 4]);
                a[tm][3] = __float_as_uint(As[m + g + 8][kk + q + 4]);
            }
#pragma unroll
            for (int tn = 0; tn < 4; tn++) {
                int n = warp_n * 32 + tn * 8 + g;
                unsigned int b0 = __float_as_uint(Ws[n][kk + q    ]);
                unsigned int b1 = __float_as_uint(Ws[n][kk + q + 4]);
#pragma unroll
                for (int tm = 0; tm < 2; tm++) {
                    asm volatile(
                        "mma.sync.aligned.m16n8k8.row.col.f32.tf32.tf32.f32 "
                        "{%0,%1,%2,%3}, {%4,%5,%6,%7}, {%8,%9}, {%0,%1,%2,%3};\n"
                        : "+f"(acc[tm][tn][0]), "+f"(acc[tm][tn][1]),
                          "+f"(acc[tm][tn][2]), "+f"(acc[tm][tn][3])
                        : "r"(a[tm][0]), "r"(a[tm][1]), "r"(a[tm][2]), "r"(a[tm][3]),
                          "r"(b0), "r"(b1));
                }
            }
        }
        __syncthreads();
    }

#pragma unroll
    for (int tm = 0; tm < 2; tm++) {
#pragma unroll
        for (int tn = 0; tn < 4; tn++) {
            int m0 = warp_m * 32 + tm * 16 + g;
            int n  = nb + warp_n * 32 + tn * 8 + q * 2;
            if (n < N) {
                *(float2*)(Cpart + (size_t)m0 * N + n) =
                    make_float2(acc[tm][tn][0], acc[tm][tn][1]);
                *(float2*)(Cpart + (size_t)(m0 + 8) * N + n) =
                    make_float2(acc[tm][tn][2], acc[tm][tn][3]);
            }
        }
    }
}

// ---------------- kernels ----------------
__global__ void __launch_bounds__(256) k_gru_gemm(
    const int* __restrict__ input, const float* __restrict__ emb,
    const float* __restrict__ hidden,
    const float* __restrict__ w_ih, const float* __restrict__ w_hh)
{
    int split = blockIdx.y;
    if (blockIdx.z == 0) {
        if (split >= SPL_GI) return;
        int ks0 = split * 64;
        int ks1 = min(ks0 + 64, EMBD);
        tf32_gemm(nullptr, EMBD, input, emb, true, w_ih, EMBD, G3H,
                  g_part_gi + (size_t)split * BB * G3H, ks0, ks1);
    } else {
        int ks0 = split * 128;
        int ks1 = ks0 + 128;
        tf32_gemm(hidden, HH, nullptr, nullptr, false, w_hh, HH, G3H,
                  g_part_gh + (size_t)split * BB * G3H, ks0, ks1);
    }
}

__global__ void k_gru(const float* __restrict__ hidden,
                      const float* __restrict__ b_ih, const float* __restrict__ b_hh,
                      float* __restrict__ out_hid)
{
    int idx = blockIdx.x * 256 + threadIdx.x;
    if (idx >= BB * HH) return;
    int b = idx / HH, j = idx % HH;
    float gir = b_ih[j], giz = b_ih[j + HH], gin = b_ih[j + 2 * HH];
    float ghr = b_hh[j], ghz = b_hh[j + HH], ghn = b_hh[j + 2 * HH];
#pragma unroll
    for (int s = 0; s < SPL_GI; s++) {
        const float* pi = g_part_gi + (size_t)s * BB * G3H + (size_t)b * G3H;
        gir += pi[j]; giz += pi[j + HH]; gin += pi[j + 2 * HH];
    }
#pragma unroll
    for (int s = 0; s < SPL_GH; s++) {
        const float* ph = g_part_gh + (size_t)s * BB * G3H + (size_t)b * G3H;
        ghr += ph[j]; ghz += ph[j + HH]; ghn += ph[j + 2 * HH];
    }
    float r = 1.f / (1.f + __expf(-(gir + ghr)));
    float z = 1.f / (1.f + __expf(-(giz + ghz)));
    float n = tanhf(gin + r * ghn);
    float hn = (1.f - z) * n + z * hidden[idx];
    g_hnew[idx] = hn;
    g_cat[(size_t)b * 2 * HH + HH + j] = hn;
    out_hid[idx] = hn;
}

__global__ void __launch_bounds__(256) k_gemm_wy(const float* __restrict__ w_attn)
{
    int split = blockIdx.y;
    int ks0 = split * 64;
    tf32_gemm(g_hnew, HH, nullptr, nullptr, false, w_attn, HH, HH,
              g_part_wy + (size_t)split * BB * HH, ks0, ks0 + 64);
}

__global__ void k_combine_wy(const float* __restrict__ b_attn)
{
    int idx = blockIdx.x * 256 + threadIdx.x;
    if (idx >= BB * HH) return;
    float v = b_attn[idx % HH];
#pragma unroll
    for (int s = 0; s < SPL_WY; s++) v += g_part_wy[(size_t)s * BB * HH + idx];
    g_wy[idx] = v;
}

__global__ void __launch_bounds__(256) k_attn1(
    const float* __restrict__ src, const int* __restrict__ mask)
{
    int b = blockIdx.y;
    int chunk = blockIdx.x;
    int l0 = chunk * 64;
    int tid = threadIdx.x, lane = tid & 31, wid = tid >> 5;

    float4 wyv[8];
#pragma unroll
    for (int qq = 0; qq < 8; qq++)
        wyv[qq] = *(const float4*)(g_wy + (size_t)b * HH + 4 * lane + 128 * qq);

    float m = -1e30f, s = 0.f;
    float4 acc[8];
#pragma unroll
    for (int qq = 0; qq < 8; qq++) acc[qq] = make_float4(0.f, 0.f, 0.f, 0.f);

    for (int i = 0; i < 8; i++) {
        int l = l0 + wid * 8 + i;
        const float* sp = src + ((size_t)l * BB + b) * HH;
        float4 v[8];
#pragma unroll
        for (int qq = 0; qq < 8; qq++)
            v[qq] = *(const float4*)(sp + 4 * lane + 128 * qq);
        float d = 0.f;
#pragma unroll
        for (int qq = 0; qq < 8; qq++) {
            d = fmaf(v[qq].x, wyv[qq].x, d);
            d = fmaf(v[qq].y, wyv[qq].y, d);
            d = fmaf(v[qq].z, wyv[qq].z, d);
            d = fmaf(v[qq].w, wyv[qq].w, d);
        }
#pragma unroll
        for (int o = 16; o > 0; o >>= 1) d += __shfl_xor_sync(0xffffffffu, d, o);
        if (mask[(size_t)b * LL + l] != 0) d = -1e30f;
        if (lane == 0) g_xwy[(size_t)b * LL + l] = d;

        float nm = fmaxf(m, d);
        float sc = __expf(m - nm);
        float p  = __expf(d - nm);
        s = s * sc + p;
#pragma unroll
        for (int qq = 0; qq < 8; qq++) {
            acc[qq].x = acc[qq].x * sc + p * v[qq].x;
            acc[qq].y = acc[qq].y * sc + p * v[qq].y;
            acc[qq].z = acc[qq].z * sc + p * v[qq].z;
            acc[qq].w = acc[qq].w * sc + p * v[qq].w;
        }
        m = nm;
    }

    __shared__ float sm[8], ss[8];
    __shared__ float sctx[8][1024];
    if (lane == 0) { sm[wid] = m; ss[wid] = s; }
    __syncthreads();
    float M = sm[0];
#pragma unroll
    for (int w = 1; w < 8; w++) M = fmaxf(M, sm[w]);
    float S = 0.f;
#pragma unroll
    for (int w = 0; w < 8; w++) S += ss[w] * __expf(sm[w] - M);

    float f = __expf(m - M);
#pragma unroll
    for (int qq = 0; qq < 8; qq++) {
        float4 t = acc[qq];
        t.x *= f; t.y *= f; t.z *= f; t.w *= f;
        *(float4*)&sctx[wid][4 * lane + 128 * qq] = t;
    }
    __syncthreads();

    int h0 = tid * 4;
    float4 tot = make_float4(0.f, 0.f, 0.f, 0.f);
#pragma unroll
    for (int w = 0; w < 8; w++) {
        float4 t = *(const float4*)&sctx[w][h0];
        tot.x += t.x; tot.y += t.y; tot.z += t.z; tot.w += t.w;
    }
    int pidx = b * 16 + chunk;
    *(float4*)(g_pctx + (size_t)pidx * HH + h0) = tot;
    if (tid == 0) { g_pm[pidx] = M; g_ps[pidx] = S; }
}

__global__ void k_attn2(float* __restrict__ out_scores)
{
    int b = blockIdx.x, t = threadIdx.x;
    __shared__ float fac[16];
    __shared__ float sM, sInvZ;
    if (t == 0) {
        float M = g_pm[b * 16];
        for (int c = 1; c < 16; c++) M = fmaxf(M, g_pm[b * 16 + c]);
        float Z = 0.f;
        for (int c = 0; c < 16; c++) Z += g_ps[b * 16 + c] * __expf(g_pm[b * 16 + c] - M);
        float invZ = 1.f / Z;
        for (int c = 0; c < 16; c++) fac[c] = __expf(g_pm[b * 16 + c] - M) * invZ;
        sM = M; sInvZ = invZ;
    }
    __syncthreads();

    int h0 = t * 4;
    float4 tot = make_float4(0.f, 0.f, 0.f, 0.f);
#pragma unroll
    for (int c = 0; c < 16; c++) {
        float4 v = *(const float4*)(g_pctx + (size_t)(b * 16 + c) * HH + h0);
        float fc = fac[c];
        tot.x += v.x * fc; tot.y += v.y * fc; tot.z += v.z * fc; tot.w += v.w * fc;
    }
    *(float4*)(g_cat + (size_t)b * 2 * HH + h0) = tot;

    float M = sM, invZ = sInvZ;
#pragma unroll
    for (int r = 0; r < 4; r++) {
        int l = t + 256 * r;
        float sc = __expf(g_xwy[(size_t)b * LL + l] - M) * invZ;
        out_scores[(size_t)b * LL + l] = sc;
    }
}

__global__ void __launch_bounds__(256) k_gemm_fu(const float* __restrict__ w_lin)
{
    int split = blockIdx.y;
    int ks0 = split * 128;
    tf32_gemm(g_cat, 2 * HH, nullptr, nullptr, false, w_lin, 2 * HH, HH,
              g_part_fu + (size_t)split * BB * HH, ks0, ks0 + 128);
}

__global__ void k_combine_fu(const float* __restrict__ b_lin)
{
    int idx = blockIdx.x * 256 + threadIdx.x;
    if (idx >= BB * HH) return;
    float v = b_lin[idx % HH];
#pragma unroll
    for (int s = 0; s < SPL_FU; s++) v += g_part_fu[(size_t)s * BB * HH + idx];
    g_fused_b16[idx] = __float2bfloat16(tanhf(v));
}

// ---------------- logits GEMM on tensor cores (bf16, reg double-buffered) ----------------
#define LBN 128
#define LBK 64
#define WPAD 72

__global__ void __launch_bounds__(256) k_logits_mma(
    const float* __restrict__ w_out, const float* __restrict__ b_out,
    float* __restrict__ out_logp)
{
    __shared__ __nv_bfloat16 As[64][WPAD];
    __shared__ __nv_bfloat16 Ws[LBN][WPAD];

    const int tid  = threadIdx.x;
    const int lane = tid & 31;
    const int wid  = tid >> 5;
    const int nb   = blockIdx.x * LBN;
    const int warp_m = wid >> 2;
    const int warp_n = wid & 3;
    const int g = lane >> 2;
    const int q = lane & 3;

    float acc[2][4][4];
#pragma unroll
    for (int tm = 0; tm < 2; tm++)
#pragma unroll
        for (int tn = 0; tn < 4; tn++)
#pragma unroll
            for (int c = 0; c < 4; c++) acc[tm][tn][c] = 0.f;

    const int ar = tid >> 2;
    const int as = tid & 3;
    const int wr = tid >> 2;
    const int wc = tid & 3;

    uint4 pa0, pa1;
    float4 pw[8];

    {
        const uint4* s4 = (const uint4*)(g_fused_b16 + (size_t)ar * HH + as * 16);
        pa0 = s4[0]; pa1 = s4[1];
#pragma unroll
        for (int half = 0; half < 2; half++) {
            int n = nb + wr + half * 64;
            const float* wp = w_out + (size_t)n * HH;
            bool ok = (n < VV);
#pragma unroll
            for (int j = 0; j < 4; j++) {
                int f4 = wc + j * 4;
                pw[half * 4 + j] = ok ? *(const float4*)(wp + f4 * 4)
                                      : make_float4(0.f, 0.f, 0.f, 0.f);
            }
        }
    }

    for (int kb = 0; kb < HH; kb += LBK) {
        *(uint4*)(&As[ar][as * 16])     = pa0;
        *(uint4*)(&As[ar][as * 16 + 8]) = pa1;
#pragma unroll
        for (int half = 0; half < 2; half++) {
#pragma unroll
            for (int j = 0; j < 4; j++) {
                int f4 = wc + j * 4;
                float4 v = pw[half * 4 + j];
                __nv_bfloat162 p0 = __floats2bfloat162_rn(v.x, v.y);
                __nv_bfloat162 p1 = __floats2bfloat162_rn(v.z, v.w);
                uint2 pk;
                pk.x = *(unsigned int*)&p0;
                pk.y = *(unsigned int*)&p1;
                *(uint2*)(&Ws[wr + half * 64][f4 * 4]) = pk;
            }
        }
        __syncthreads();

        if (kb + LBK < HH) {
            int kn = kb + LBK;
            const uint4* s4 = (const uint4*)(g_fused_b16 + (size_t)ar * HH + kn + as * 16);
            pa0 = s4[0]; pa1 = s4[1];
#pragma unroll
            for (int half = 0; half < 2; half++) {
                int n = nb + wr + half * 64;
                const float* wp = w_out + (size_t)n * HH + kn;
                bool ok = (n < VV);
#pragma unroll
                for (int j = 0; j < 4; j++) {
                    int f4 = wc + j * 4;
                    pw[half * 4 + j] = ok ? *(const float4*)(wp + f4 * 4)
                                          : make_float4(0.f, 0.f, 0.f, 0.f);
                }
            }
        }

#pragma unroll
        for (int kk = 0; kk < LBK; kk += 16) {
            unsigned int a[2][4];
#pragma unroll
            for (int tm = 0; tm < 2; tm++) {
                int m = warp_m * 32 + tm * 16;
                a[tm][0] = *(const unsigned int*)&As[m + g    ][kk + q * 2];
                a[tm][1] = *(const unsigned int*)&As[m + g + 8][kk + q * 2];
                a[tm][2] = *(const unsigned int*)&As[m + g    ][kk + 8 + q * 2];
                a[tm][3] = *(const unsigned int*)&As[m + g + 8][kk + 8 + q * 2];
            }
#pragma unroll
            for (int tn = 0; tn < 4; tn++) {
                int n = warp_n * 32 + tn * 8;
                unsigned int b0 = *(const unsigned int*)&Ws[n + g][kk + q * 2];
                unsigned int b1 = *(const unsigned int*)&Ws[n + g][kk + 8 + q * 2];
#pragma unroll
                for (int tm = 0; tm < 2; tm++) {
                    asm volatile(
                        "mma.sync.aligned.m16n8k16.row.col.f32.bf16.bf16.f32 "
                        "{%0,%1,%2,%3}, {%4,%5,%6,%7}, {%8,%9}, {%0,%1,%2,%3};\n"
                        : "+f"(acc[tm][tn][0]), "+f"(acc[tm][tn][1]),
                          "+f"(acc[tm][tn][2]), "+f"(acc[tm][tn][3])
                        : "r"(a[tm][0]), "r"(a[tm][1]), "r"(a[tm][2]), "r"(a[tm][3]),
                          "r"(b0), "r"(b1));
                }
            }
        }
        __syncthreads();
    }

#pragma unroll
    for (int tm = 0; tm < 2; tm++) {
#pragma unroll
        for (int tn = 0; tn < 4; tn++) {
            int m0 = warp_m * 32 + tm * 16 + g;
            int n  = nb + warp_n * 32 + tn * 8 + q * 2;
            if (n + 1 < VV) {
                float bz0 = b_out[n], bz1 = b_out[n + 1];
                *(float2*)(out_logp + (size_t)m0 * VV + n) =
                    make_float2(acc[tm][tn][0] + bz0, acc[tm][tn][1] + bz1);
                *(float2*)(out_logp + (size_t)(m0 + 8) * VV + n) =
                    make_float2(acc[tm][tn][2] + bz0, acc[tm][tn][3] + bz1);
            } else {
                for (int c = 0; c < 2; c++) {
                    if (n + c < VV) {
                        float bz = b_out[n + c];
                        out_logp[(size_t)m0 * VV + n + c]       = acc[tm][tn][c] + bz;
                        out_logp[(size_t)(m0 + 8) * VV + n + c] = acc[tm][tn][2 + c] + bz;
                    }
                }
            }
        }
    }
}

__global__ void k_lse(const float* __restrict__ logits)
{
    int b = blockIdx.x, t = threadIdx.x;
    float m = -1e30f, s = 0.f;
    for (int n = t; n < VV; n += 512) {
        float v = logits[(size_t)b * VV + n];
        float nm = fmaxf(m, v);
        s = s * __expf(m - nm) + __expf(v - nm);
        m = nm;
    }
    __shared__ float sm[512], ss[512];
    sm[t] = m; ss[t] = s;
    __syncthreads();
    for (int o = 256; o > 0; o >>= 1) {
        if (t < o) {
            float m2 = sm[t + o], s2 = ss[t + o];
            float nm = fmaxf(sm[t], m2);
            ss[t] = ss[t] * __expf(sm[t] - nm) + s2 * __expf(m2 - nm);
            sm[t] = nm;
        }
        __syncthreads();
    }
    if (t == 0) g_lse[b] = sm[0] + logf(ss[0]);
}

__global__ void k_sub(float* __restrict__ logp)
{
    int n = blockIdx.x * 256 + threadIdx.x;
    int b = blockIdx.y;
    if (n < VV) logp[(size_t)b * VV + n] -= g_lse[b];
}

// ---------------- launcher ----------------
extern "C" void kernel_launch(void* const* d_in, const int* in_sizes, int n_in,
                              void* d_out, int out_size)
{
    const int*   input  = (const int*)  d_in[0];
    const float* hidden = (const float*)d_in[1];
    const float* src    = (const float*)d_in[2];
    const int*   mask   = (const int*)  d_in[3];
    const float* emb    = (const float*)d_in[4];
    const float* w_ih   = (const float*)d_in[5];
    const float* w_hh   = (const float*)d_in[6];
    const float* b_ih   = (const float*)d_in[7];
    const float* b_hh   = (const float*)d_in[8];
    const float* w_attn = (const float*)d_in[9];
    const float* b_attn = (const float*)d_in[10];
    const float* w_lin  = (const float*)d_in[11];
    const float* b_lin  = (const float*)d_in[12];
    const float* w_out  = (const float*)d_in[13];
    const float* b_out  = (const float*)d_in[14];

    float* out        = (float*)d_out;
    float* out_logp   = out;                                   // [64 x 50004]
    float* out_hid    = out + (size_t)BB * VV;                 // [1 x 64 x 1024]
    float* out_scores = out_hid + (size_t)BB * HH;             // [64 x 1024]

    k_gru_gemm<<<dim3(24, 8, 2), 256>>>(input, emb, hidden, w_ih, w_hh);
    k_gru<<<(BB * HH + 255) / 256, 256>>>(hidden, b_ih, b_hh, out_hid);
    k_gemm_wy<<<dim3(8, SPL_WY), 256>>>(w_attn);
    k_combine_wy<<<(BB * HH + 255) / 256, 256>>>(b_attn);
    k_attn1<<<dim3(16, BB), 256>>>(src, mask);
    k_attn2<<<BB, 256>>>(out_scores);
    k_gemm_fu<<<dim3(8, SPL_FU), 256>>>(w_lin);
    k_combine_fu<<<(BB * HH + 255) / 256, 256>>>(b_lin);
    k_logits_mma<<<(VV + LBN - 1) / LBN, 256>>>(w_out, b_out, out_logp);
    k_lse<<<BB, 512>>>(out_logp);
    k_sub<<<dim3((VV + 255) / 256, BB), 256>>>(out_logp);
}

// round 4
// speedup vs baseline: 1.9170x; 1.0126x over previous
#include <cuda_runtime.h>
#include <cuda_bf16.h>
#include <math.h>

#define BB 64
#define HH 1024
#define EMBD 300
#define VV 50004
#define VV4 12501
#define LL 1024
#define G3H 3072

// split counts
#define SPL_GI 5     // K=300, 64-chunks
#define SPL_GH 8     // K=1024, 128-slices
#define SPL_WY 16    // K=1024, 64-slices
#define SPL_FU 16    // K=2048, 128-slices
#define LSE_CH 16

// ---------------- scratch (static device memory; no allocations) ----------------
__device__ float g_part_gi[SPL_GI * BB * G3H];
__device__ float g_part_gh[SPL_GH * BB * G3H];
__device__ float g_hnew[BB * HH];
__device__ float g_cat[BB * 2 * HH];       // [context | h_new]
__device__ float g_part_wy[SPL_WY * BB * HH];
__device__ float g_wy[BB * HH];
__device__ float g_xwy[BB * LL];
__device__ float g_pm[BB * 16];
__device__ float g_ps[BB * 16];
__device__ float g_pctx[BB * 16 * HH];
__device__ float g_part_fu[SPL_FU * BB * HH];
__device__ __nv_bfloat16 g_fused_b16[BB * HH];
__device__ float g_lsm[BB * LSE_CH];
__device__ float g_lss[BB * LSE_CH];
__device__ float g_lse[BB];

__device__ __forceinline__ float to_tf32(float x)
{
    float r;
    asm("cvt.rna.tf32.f32 %0, %1;" : "=f"(r) : "f"(x));
    return r;
}

// ---------------- 3xTF32 tensor-core GEMM (small GEMMs, near-fp32 accuracy) ----------------
// Cpart[64 x N] = A[64 x k-slice] @ W[N x K]^T over k in [ks0, ks1)
// tile 64 x 128, 256 threads, 8 warps = 2(m) x 4(n), BK = 32
// operands split hi/lo; acc += Ahi*Bhi + Ahi*Blo + Alo*Bhi
__device__ __forceinline__ void tf32_gemm(
    const float* __restrict__ A, int lda,
    const int* __restrict__ inp, const float* __restrict__ emb, bool gather,
    const float* __restrict__ W, int ldw, int N,
    float* __restrict__ Cpart, int ks0, int ks1)
{
    __shared__ float As[2][64][36];
    __shared__ float Ws[2][128][36];

    const int tid  = threadIdx.x;
    const int lane = tid & 31;
    const int wid  = tid >> 5;
    const int nb   = blockIdx.x * 128;
    const int warp_m = wid >> 2;
    const int warp_n = wid & 3;
    const int g = lane >> 2;
    const int q = lane & 3;

    float acc[2][4][4];
#pragma unroll
    for (int tm = 0; tm < 2; tm++)
#pragma unroll
        for (int tn = 0; tn < 4; tn++)
#pragma unroll
            for (int c = 0; c < 4; c++) acc[tm][tn][c] = 0.f;

    for (int kb = ks0; kb < ks1; kb += 32) {
#pragma unroll
        for (int t = 0; t < 2; t++) {
            int idx = tid + 256 * t;
            int row = idx >> 3;
            int c4  = idx & 7;
            int k0  = kb + c4 * 4;
            float4 v = make_float4(0.f, 0.f, 0.f, 0.f);
            if (k0 + 4 <= ks1) {
                const float* ap = gather ? (emb + (size_t)inp[row] * lda)
                                         : (A + (size_t)row * lda);
                v = *(const float4*)(ap + k0);
            }
            float hx = to_tf32(v.x), hy = to_tf32(v.y),
                  hz = to_tf32(v.z), hw = to_tf32(v.w);
            As[0][row][c4 * 4 + 0] = hx;
            As[0][row][c4 * 4 + 1] = hy;
            As[0][row][c4 * 4 + 2] = hz;
            As[0][row][c4 * 4 + 3] = hw;
            As[1][row][c4 * 4 + 0] = to_tf32(v.x - hx);
            As[1][row][c4 * 4 + 1] = to_tf32(v.y - hy);
            As[1][row][c4 * 4 + 2] = to_tf32(v.z - hz);
            As[1][row][c4 * 4 + 3] = to_tf32(v.w - hw);
        }
#pragma unroll
        for (int t = 0; t < 4; t++) {
            int idx = tid + 256 * t;
            int row = idx >> 3;
            int c4  = idx & 7;
            int k0  = kb + c4 * 4;
            int n   = nb + row;
            float4 v = make_float4(0.f, 0.f, 0.f, 0.f);
            if (n < N && k0 + 4 <= ks1)
                v = *(const float4*)(W + (size_t)n * ldw + k0);
            float hx = to_tf32(v.x), hy = to_tf32(v.y),
                  hz = to_tf32(v.z), hw = to_tf32(v.w);
            Ws[0][row][c4 * 4 + 0] = hx;
            Ws[0][row][c4 * 4 + 1] = hy;
            Ws[0][row][c4 * 4 + 2] = hz;
            Ws[0][row][c4 * 4 + 3] = hw;
            Ws[1][row][c4 * 4 + 0] = to_tf32(v.x - hx);
            Ws[1][row][c4 * 4 + 1] = to_tf32(v.y - hy);
            Ws[1][row][c4 * 4 + 2] = to_tf32(v.z - hz);
            Ws[1][row][c4 * 4 + 3] = to_tf32(v.w - hw);
        }
        __syncthreads();

#pragma unroll
        for (int kk = 0; kk < 32; kk += 8) {
            unsigned int ah[2][4], al[2][4];
#pragma unroll
            for (int tm = 0; tm < 2; tm++) {
                int m = warp_m * 32 + tm * 16;
                ah[tm][0] = __float_as_uint(As[0][m + g    ][kk + q    ]);
                ah[tm][1] = __float_as_uint(As[0][m + g + 8][kk + q    ]);
                ah[tm][2] = __float_as_uint(As[0][m + g    ][kk + q + 4]);
                ah[tm][3] = __float_as_uint(As[0][m + g + 8][kk + q + 4]);
                al[tm][0] = __float_as_uint(As[1][m + g    ][kk + q    ]);
                al[tm][1] = __float_as_uint(As[1][m + g + 8][kk + q    ]);
                al[tm][2] = __float_as_uint(As[1][m + g    ][kk + q + 4]);
                al[tm][3] = __float_as_uint(As[1][m + g + 8][kk + q + 4]);
            }
#pragma unroll
            for (int tn = 0; tn < 4; tn++) {
                int n = warp_n * 32 + tn * 8 + g;
                unsigned int bh0 = __float_as_uint(Ws[0][n][kk + q    ]);
                unsigned int bh1 = __float_as_uint(Ws[0][n][kk + q + 4]);
                unsigned int bl0 = __float_as_uint(Ws[1][n][kk + q    ]);
                unsigned int bl1 = __float_as_uint(Ws[1][n][kk + q + 4]);
#pragma unroll
                for (int tm = 0; tm < 2; tm++) {
                    // lo terms first, hi*hi last
                    asm volatile(
                        "mma.sync.aligned.m16n8k8.row.col.f32.tf32.tf32.f32 "
                        "{%0,%1,%2,%3}, {%4,%5,%6,%7}, {%8,%9}, {%0,%1,%2,%3};\n"
                        : "+f"(acc[tm][tn][0]), "+f"(acc[tm][tn][1]),
                          "+f"(acc[tm][tn][2]), "+f"(acc[tm][tn][3])
                        : "r"(al[tm][0]), "r"(al[tm][1]), "r"(al[tm][2]), "r"(al[tm][3]),
                          "r"(bh0), "r"(bh1));
                    asm volatile(
                        "mma.sync.aligned.m16n8k8.row.col.f32.tf32.tf32.f32 "
                        "{%0,%1,%2,%3}, {%4,%5,%6,%7}, {%8,%9}, {%0,%1,%2,%3};\n"
                        : "+f"(acc[tm][tn][0]), "+f"(acc[tm][tn][1]),
                          "+f"(acc[tm][tn][2]), "+f"(acc[tm][tn][3])
                        : "r"(ah[tm][0]), "r"(ah[tm][1]), "r"(ah[tm][2]), "r"(ah[tm][3]),
                          "r"(bl0), "r"(bl1));
                    asm volatile(
                        "mma.sync.aligned.m16n8k8.row.col.f32.tf32.tf32.f32 "
                        "{%0,%1,%2,%3}, {%4,%5,%6,%7}, {%8,%9}, {%0,%1,%2,%3};\n"
                        : "+f"(acc[tm][tn][0]), "+f"(acc[tm][tn][1]),
                          "+f"(acc[tm][tn][2]), "+f"(acc[tm][tn][3])
                        : "r"(ah[tm][0]), "r"(ah[tm][1]), "r"(ah[tm][2]), "r"(ah[tm][3]),
                          "r"(bh0), "r"(bh1));
                }
            }
        }
        __syncthreads();
    }

#pragma unroll
    for (int tm = 0; tm < 2; tm++) {
#pragma unroll
        for (int tn = 0; tn < 4; tn++) {
            int m0 = warp_m * 32 + tm * 16 + g;
            int n  = nb + warp_n * 32 + tn * 8 + q * 2;
            if (n < N) {
                *(float2*)(Cpart + (size_t)m0 * N + n) =
                    make_float2(acc[tm][tn][0], acc[tm][tn][1]);
                *(float2*)(Cpart + (size_t)(m0 + 8) * N + n) =
                    make_float2(acc[tm][tn][2], acc[tm][tn][3]);
            }
        }
    }
}

// ---------------- kernels ----------------
__global__ void __launch_bounds__(256) k_gru_gemm(
    const int* __restrict__ input, const float* __restrict__ emb,
    const float* __restrict__ hidden,
    const float* __restrict__ w_ih, const float* __restrict__ w_hh)
{
    int split = blockIdx.y;
    if (blockIdx.z == 0) {
        if (split >= SPL_GI) return;
        int ks0 = split * 64;
        int ks1 = min(ks0 + 64, EMBD);
        tf32_gemm(nullptr, EMBD, input, emb, true, w_ih, EMBD, G3H,
                  g_part_gi + (size_t)split * BB * G3H, ks0, ks1);
    } else {
        int ks0 = split * 128;
        int ks1 = ks0 + 128;
        tf32_gemm(hidden, HH, nullptr, nullptr, false, w_hh, HH, G3H,
                  g_part_gh + (size_t)split * BB * G3H, ks0, ks1);
    }
}

__global__ void k_gru(const float* __restrict__ hidden,
                      const float* __restrict__ b_ih, const float* __restrict__ b_hh,
                      float* __restrict__ out_hid)
{
    int idx = blockIdx.x * 256 + threadIdx.x;
    if (idx >= BB * HH) return;
    int b = idx / HH, j = idx % HH;
    float gir = b_ih[j], giz = b_ih[j + HH], gin = b_ih[j + 2 * HH];
    float ghr = b_hh[j], ghz = b_hh[j + HH], ghn = b_hh[j + 2 * HH];
#pragma unroll
    for (int s = 0; s < SPL_GI; s++) {
        const float* pi = g_part_gi + (size_t)s * BB * G3H + (size_t)b * G3H;
        gir += pi[j]; giz += pi[j + HH]; gin += pi[j + 2 * HH];
    }
#pragma unroll
    for (int s = 0; s < SPL_GH; s++) {
        const float* ph = g_part_gh + (size_t)s * BB * G3H + (size_t)b * G3H;
        ghr += ph[j]; ghz += ph[j + HH]; ghn += ph[j + 2 * HH];
    }
    float r = 1.f / (1.f + __expf(-(gir + ghr)));
    float z = 1.f / (1.f + __expf(-(giz + ghz)));
    float n = tanhf(gin + r * ghn);
    float hn = (1.f - z) * n + z * hidden[idx];
    g_hnew[idx] = hn;
    g_cat[(size_t)b * 2 * HH + HH + j] = hn;
    out_hid[idx] = hn;
}

__global__ void __launch_bounds__(256) k_gemm_wy(const float* __restrict__ w_attn)
{
    int split = blockIdx.y;
    int ks0 = split * 64;
    tf32_gemm(g_hnew, HH, nullptr, nullptr, false, w_attn, HH, HH,
              g_part_wy + (size_t)split * BB * HH, ks0, ks0 + 64);
}

__global__ void k_combine_wy(const float* __restrict__ b_attn)
{
    int idx = blockIdx.x * 256 + threadIdx.x;
    if (idx >= BB * HH) return;
    float v = b_attn[idx % HH];
#pragma unroll
    for (int s = 0; s < SPL_WY; s++) v += g_part_wy[(size_t)s * BB * HH + idx];
    g_wy[idx] = v;
}

__global__ void __launch_bounds__(256) k_attn1(
    const float* __restrict__ src, const int* __restrict__ mask)
{
    int b = blockIdx.y;
    int chunk = blockIdx.x;
    int l0 = chunk * 64;
    int tid = threadIdx.x, lane = tid & 31, wid = tid >> 5;

    float4 wyv[8];
#pragma unroll
    for (int qq = 0; qq < 8; qq++)
        wyv[qq] = *(const float4*)(g_wy + (size_t)b * HH + 4 * lane + 128 * qq);

    float m = -1e30f, s = 0.f;
    float4 acc[8];
#pragma unroll
    for (int qq = 0; qq < 8; qq++) acc[qq] = make_float4(0.f, 0.f, 0.f, 0.f);

    for (int i = 0; i < 8; i++) {
        int l = l0 + wid * 8 + i;
        const float* sp = src + ((size_t)l * BB + b) * HH;
        float4 v[8];
#pragma unroll
        for (int qq = 0; qq < 8; qq++)
            v[qq] = *(const float4*)(sp + 4 * lane + 128 * qq);
        float d = 0.f;
#pragma unroll
        for (int qq = 0; qq < 8; qq++) {
            d = fmaf(v[qq].x, wyv[qq].x, d);
            d = fmaf(v[qq].y, wyv[qq].y, d);
            d = fmaf(v[qq].z, wyv[qq].z, d);
            d = fmaf(v[qq].w, wyv[qq].w, d);
        }
#pragma unroll
        for (int o = 16; o > 0; o >>= 1) d += __shfl_xor_sync(0xffffffffu, d, o);
        if (mask[(size_t)b * LL + l] != 0) d = -1e30f;
        if (lane == 0) g_xwy[(size_t)b * LL + l] = d;

        float nm = fmaxf(m, d);
        float sc = __expf(m - nm);
        float p  = __expf(d - nm);
        s = s * sc + p;
#pragma unroll
        for (int qq = 0; qq < 8; qq++) {
            acc[qq].x = acc[qq].x * sc + p * v[qq].x;
            acc[qq].y = acc[qq].y * sc + p * v[qq].y;
            acc[qq].z = acc[qq].z * sc + p * v[qq].z;
            acc[qq].w = acc[qq].w * sc + p * v[qq].w;
        }
        m = nm;
    }

    __shared__ float sm[8], ss[8];
    __shared__ float sctx[8][1024];
    if (lane == 0) { sm[wid] = m; ss[wid] = s; }
    __syncthreads();
    float M = sm[0];
#pragma unroll
    for (int w = 1; w < 8; w++) M = fmaxf(M, sm[w]);
    float S = 0.f;
#pragma unroll
    for (int w = 0; w < 8; w++) S += ss[w] * __expf(sm[w] - M);

    float f = __expf(m - M);
#pragma unroll
    for (int qq = 0; qq < 8; qq++) {
        float4 t = acc[qq];
        t.x *= f; t.y *= f; t.z *= f; t.w *= f;
        *(float4*)&sctx[wid][4 * lane + 128 * qq] = t;
    }
    __syncthreads();

    int h0 = tid * 4;
    float4 tot = make_float4(0.f, 0.f, 0.f, 0.f);
#pragma unroll
    for (int w = 0; w < 8; w++) {
        float4 t = *(const float4*)&sctx[w][h0];
        tot.x += t.x; tot.y += t.y; tot.z += t.z; tot.w += t.w;
    }
    int pidx = b * 16 + chunk;
    *(float4*)(g_pctx + (size_t)pidx * HH + h0) = tot;
    if (tid == 0) { g_pm[pidx] = M; g_ps[pidx] = S; }
}

__global__ void k_attn2(float* __restrict__ out_scores)
{
    int b = blockIdx.x, t = threadIdx.x;
    __shared__ float fac[16];
    __shared__ float sM, sInvZ;
    if (t == 0) {
        float M = g_pm[b * 16];
        for (int c = 1; c < 16; c++) M = fmaxf(M, g_pm[b * 16 + c]);
        float Z = 0.f;
        for (int c = 0; c < 16; c++) Z += g_ps[b * 16 + c] * __expf(g_pm[b * 16 + c] - M);
        float invZ = 1.f / Z;
        for (int c = 0; c < 16; c++) fac[c] = __expf(g_pm[b * 16 + c] - M) * invZ;
        sM = M; sInvZ = invZ;
    }
    __syncthreads();

    int h0 = t * 4;
    float4 tot = make_float4(0.f, 0.f, 0.f, 0.f);
#pragma unroll
    for (int c = 0; c < 16; c++) {
        float4 v = *(const float4*)(g_pctx + (size_t)(b * 16 + c) * HH + h0);
        float fc = fac[c];
        tot.x += v.x * fc; tot.y += v.y * fc; tot.z += v.z * fc; tot.w += v.w * fc;
    }
    *(float4*)(g_cat + (size_t)b * 2 * HH + h0) = tot;

    float M = sM, invZ = sInvZ;
#pragma unroll
    for (int r = 0; r < 4; r++) {
        int l = t + 256 * r;
        float sc = __expf(g_xwy[(size_t)b * LL + l] - M) * invZ;
        out_scores[(size_t)b * LL + l] = sc;
    }
}

__global__ void __launch_bounds__(256) k_gemm_fu(const float* __restrict__ w_lin)
{
    int split = blockIdx.y;
    int ks0 = split * 128;
    tf32_gemm(g_cat, 2 * HH, nullptr, nullptr, false, w_lin, 2 * HH, HH,
              g_part_fu + (size_t)split * BB * HH, ks0, ks0 + 128);
}

__global__ void k_combine_fu(const float* __restrict__ b_lin)
{
    int idx = blockIdx.x * 256 + threadIdx.x;
    if (idx >= BB * HH) return;
    float v = b_lin[idx % HH];
#pragma unroll
    for (int s = 0; s < SPL_FU; s++) v += g_part_fu[(size_t)s * BB * HH + idx];
    g_fused_b16[idx] = __float2bfloat16(tanhf(v));
}

// ---------------- logits GEMM on tensor cores (bf16, reg double-buffered) ----------------
#define LBN 128
#define LBK 64
#define WPAD 72

__global__ void __launch_bounds__(256) k_logits_mma(
    const float* __restrict__ w_out, const float* __restrict__ b_out,
    float* __restrict__ out_logp)
{
    __shared__ __nv_bfloat16 As[64][WPAD];
    __shared__ __nv_bfloat16 Ws[LBN][WPAD];

    const int tid  = threadIdx.x;
    const int lane = tid & 31;
    const int wid  = tid >> 5;
    const int nb   = blockIdx.x * LBN;
    const int warp_m = wid >> 2;
    const int warp_n = wid & 3;
    const int g = lane >> 2;
    const int q = lane & 3;

    float acc[2][4][4];
#pragma unroll
    for (int tm = 0; tm < 2; tm++)
#pragma unroll
        for (int tn = 0; tn < 4; tn++)
#pragma unroll
            for (int c = 0; c < 4; c++) acc[tm][tn][c] = 0.f;

    const int ar = tid >> 2;
    const int as = tid & 3;
    const int wr = tid >> 2;
    const int wc = tid & 3;

    uint4 pa0, pa1;
    float4 pw[8];

    {
        const uint4* s4 = (const uint4*)(g_fused_b16 + (size_t)ar * HH + as * 16);
        pa0 = s4[0]; pa1 = s4[1];
#pragma unroll
        for (int half = 0; half < 2; half++) {
            int n = nb + wr + half * 64;
            const float* wp = w_out + (size_t)n * HH;
            bool ok = (n < VV);
#pragma unroll
            for (int j = 0; j < 4; j++) {
                int f4 = wc + j * 4;
                pw[half * 4 + j] = ok ? *(const float4*)(wp + f4 * 4)
                                      : make_float4(0.f, 0.f, 0.f, 0.f);
            }
        }
    }

    for (int kb = 0; kb < HH; kb += LBK) {
        *(uint4*)(&As[ar][as * 16])     = pa0;
        *(uint4*)(&As[ar][as * 16 + 8]) = pa1;
#pragma unroll
        for (int half = 0; half < 2; half++) {
#pragma unroll
            for (int j = 0; j < 4; j++) {
                int f4 = wc + j * 4;
                float4 v = pw[half * 4 + j];
                __nv_bfloat162 p0 = __floats2bfloat162_rn(v.x, v.y);
                __nv_bfloat162 p1 = __floats2bfloat162_rn(v.z, v.w);
                uint2 pk;
                pk.x = *(unsigned int*)&p0;
                pk.y = *(unsigned int*)&p1;
                *(uint2*)(&Ws[wr + half * 64][f4 * 4]) = pk;
            }
        }
        __syncthreads();

        if (kb + LBK < HH) {
            int kn = kb + LBK;
            const uint4* s4 = (const uint4*)(g_fused_b16 + (size_t)ar * HH + kn + as * 16);
            pa0 = s4[0]; pa1 = s4[1];
#pragma unroll
            for (int half = 0; half < 2; half++) {
                int n = nb + wr + half * 64;
                const float* wp = w_out + (size_t)n * HH + kn;
                bool ok = (n < VV);
#pragma unroll
                for (int j = 0; j < 4; j++) {
                    int f4 = wc + j * 4;
                    pw[half * 4 + j] = ok ? *(const float4*)(wp + f4 * 4)
                                          : make_float4(0.f, 0.f, 0.f, 0.f);
                }
            }
        }

#pragma unroll
        for (int kk = 0; kk < LBK; kk += 16) {
            unsigned int a[2][4];
#pragma unroll
            for (int tm = 0; tm < 2; tm++) {
                int m = warp_m * 32 + tm * 16;
                a[tm][0] = *(const unsigned int*)&As[m + g    ][kk + q * 2];
                a[tm][1] = *(const unsigned int*)&As[m + g + 8][kk + q * 2];
                a[tm][2] = *(const unsigned int*)&As[m + g    ][kk + 8 + q * 2];
                a[tm][3] = *(const unsigned int*)&As[m + g + 8][kk + 8 + q * 2];
            }
#pragma unroll
            for (int tn = 0; tn < 4; tn++) {
                int n = warp_n * 32 + tn * 8;
                unsigned int b0 = *(const unsigned int*)&Ws[n + g][kk + q * 2];
                unsigned int b1 = *(const unsigned int*)&Ws[n + g][kk + 8 + q * 2];
#pragma unroll
                for (int tm = 0; tm < 2; tm++) {
                    asm volatile(
                        "mma.sync.aligned.m16n8k16.row.col.f32.bf16.bf16.f32 "
                        "{%0,%1,%2,%3}, {%4,%5,%6,%7}, {%8,%9}, {%0,%1,%2,%3};\n"
                        : "+f"(acc[tm][tn][0]), "+f"(acc[tm][tn][1]),
                          "+f"(acc[tm][tn][2]), "+f"(acc[tm][tn][3])
                        : "r"(a[tm][0]), "r"(a[tm][1]), "r"(a[tm][2]), "r"(a[tm][3]),
                          "r"(b0), "r"(b1));
                }
            }
        }
        __syncthreads();
    }

#pragma unroll
    for (int tm = 0; tm < 2; tm++) {
#pragma unroll
        for (int tn = 0; tn < 4; tn++) {
            int m0 = warp_m * 32 + tm * 16 + g;
            int n  = nb + warp_n * 32 + tn * 8 + q * 2;
            if (n + 1 < VV) {
                float bz0 = b_out[n], bz1 = b_out[n + 1];
                *(float2*)(out_logp + (size_t)m0 * VV + n) =
                    make_float2(acc[tm][tn][0] + bz0, acc[tm][tn][1] + bz1);
                *(float2*)(out_logp + (size_t)(m0 + 8) * VV + n) =
                    make_float2(acc[tm][tn][2] + bz0, acc[tm][tn][3] + bz1);
            } else {
                for (int c = 0; c < 2; c++) {
                    if (n + c < VV) {
                        float bz = b_out[n + c];
                        out_logp[(size_t)m0 * VV + n + c]       = acc[tm][tn][c] + bz;
                        out_logp[(size_t)(m0 + 8) * VV + n + c] = acc[tm][tn][2 + c] + bz;
                    }
                }
            }
        }
    }
}

// two-stage logsumexp: stage 1, grid (64, LSE_CH)
__global__ void k_lse1(const float* __restrict__ logits)
{
    int b = blockIdx.x, c = blockIdx.y, t = threadIdx.x;
    const int chunk = (VV + LSE_CH - 1) / LSE_CH;   // 3126
    int n0 = c * chunk;
    int n1 = min(n0 + chunk, VV);

    float m = -1e30f, s = 0.f;
    for (int n = n0 + t; n < n1; n += 256) {
        float v = logits[(size_t)b * VV + n];
        float nm = fmaxf(m, v);
        s = s * __expf(m - nm) + __expf(v - nm);
        m = nm;
    }
#pragma unroll
    for (int o = 16; o > 0; o >>= 1) {
        float m2 = __shfl_xor_sync(0xffffffffu, m, o);
        float s2 = __shfl_xor_sync(0xffffffffu, s, o);
        float nm = fmaxf(m, m2);
        s = s * __expf(m - nm) + s2 * __expf(m2 - nm);
        m = nm;
    }
    __shared__ float sm[8], ss[8];
    int lane = t & 31, wid = t >> 5;
    if (lane == 0) { sm[wid] = m; ss[wid] = s; }
    __syncthreads();
    if (t == 0) {
        float M = sm[0], S = ss[0];
#pragma unroll
        for (int w = 1; w < 8; w++) {
            float nm = fmaxf(M, sm[w]);
            S = S * __expf(M - nm) + ss[w] * __expf(sm[w] - nm);
            M = nm;
        }
        g_lsm[b * LSE_CH + c] = M;
        g_lss[b * LSE_CH + c] = S;
    }
}

// stage 2: 1 block, 64 threads
__global__ void k_lse2()
{
    int b = threadIdx.x;
    if (b >= BB) return;
    float M = g_lsm[b * LSE_CH];
#pragma unroll
    for (int c = 1; c < LSE_CH; c++) M = fmaxf(M, g_lsm[b * LSE_CH + c]);
    float S = 0.f;
#pragma unroll
    for (int c = 0; c < LSE_CH; c++)
        S += g_lss[b * LSE_CH + c] * __expf(g_lsm[b * LSE_CH + c] - M);
    g_lse[b] = M + logf(S);
}

__global__ void k_sub(float* __restrict__ logp)
{
    int n4 = blockIdx.x * 256 + threadIdx.x;
    int b  = blockIdx.y;
    if (n4 < VV4) {
        float l = g_lse[b];
        float4* p = (float4*)(logp + (size_t)b * VV) + n4;
        float4 v = *p;
        v.x -= l; v.y -= l; v.z -= l; v.w -= l;
        *p = v;
    }
}

// ---------------- launcher ----------------
extern "C" void kernel_launch(void* const* d_in, const int* in_sizes, int n_in,
                              void* d_out, int out_size)
{
    const int*   input  = (const int*)  d_in[0];
    const float* hidden = (const float*)d_in[1];
    const float* src    = (const float*)d_in[2];
    const int*   mask   = (const int*)  d_in[3];
    const float* emb    = (const float*)d_in[4];
    const float* w_ih   = (const float*)d_in[5];
    const float* w_hh   = (const float*)d_in[6];
    const float* b_ih   = (const float*)d_in[7];
    const float* b_hh   = (const float*)d_in[8];
    const float* w_attn = (const float*)d_in[9];
    const float* b_attn = (const float*)d_in[10];
    const float* w_lin  = (const float*)d_in[11];
    const float* b_lin  = (const float*)d_in[12];
    const float* w_out  = (const float*)d_in[13];
    const float* b_out  = (const float*)d_in[14];

    float* out        = (float*)d_out;
    float* out_logp   = out;                                   // [64 x 50004]
    float* out_hid    = out + (size_t)BB * VV;                 // [1 x 64 x 1024]
    float* out_scores = out_hid + (size_t)BB * HH;             // [64 x 1024]

    k_gru_gemm<<<dim3(24, 8, 2), 256>>>(input, emb, hidden, w_ih, w_hh);
    k_gru<<<(BB * HH + 255) / 256, 256>>>(hidden, b_ih, b_hh, out_hid);
    k_gemm_wy<<<dim3(8, SPL_WY), 256>>>(w_attn);
    k_combine_wy<<<(BB * HH + 255) / 256, 256>>>(b_attn);
    k_attn1<<<dim3(16, BB), 256>>>(src, mask);
    k_attn2<<<BB, 256>>>(out_scores);
    k_gemm_fu<<<dim3(8, SPL_FU), 256>>>(w_lin);
    k_combine_fu<<<(BB * HH + 255) / 256, 256>>>(b_lin);
    k_logits_mma<<<(VV + LBN - 1) / LBN, 256>>>(w_out, b_out, out_logp);
    k_lse1<<<dim3(BB, LSE_CH), 256>>>(out_logp);
    k_lse2<<<1, 64>>>();
    k_sub<<<dim3((VV4 + 255) / 256, BB), 256>>>(out_logp);
}